// round 11
// baseline (speedup 1.0000x reference)
#include <cuda_runtime.h>
#include <cuda_fp16.h>
#include <mma.h>
using namespace nvcuda;

#define NN 50000
#define NPAD 50048     // NN rounded up to 128 (GEMM tile)
#define EE 800000
#define TT (EE + NN)
#define HH 4
#define CHN 256        // H * C (both layers)
#define C2  64

// ---------------- scratch (device globals; no allocation allowed) ----------
__device__ __align__(16) __half g_h16[(size_t)NPAD * CHN];  // GEMM out (fp16)
__device__ __align__(16) __half g_x1h[(size_t)NPAD * CHN];  // relu(layer1 out), fp16
__device__ __align__(16) float g_as[NN * HH];
__device__ __align__(16) float g_ad[NN * HH];
__device__ __align__(16) float g_e[(size_t)TT * HH];        // CSR-ordered logits
__device__ int   g_deg[NN];
__device__ int   g_rowptr[NN + 1];
__device__ int   g_cursor[NN];
__device__ int   g_srcs[TT];

// ---------------- CSR build -------------------------------------------------
__global__ void k_zero_deg() {
    int i = blockIdx.x * blockDim.x + threadIdx.x;
    if (i < NN) g_deg[i] = 0;
}

__global__ void k_hist(const int* __restrict__ ei) {
    int t = blockIdx.x * blockDim.x + threadIdx.x;
    if (t >= TT) return;
    int d = (t < EE) ? ei[EE + t] : (t - EE);
    atomicAdd(&g_deg[d], 1);
}

__global__ void k_scan() {
    __shared__ int s[1024];
    const int tid = threadIdx.x;
    const int CHK = (NN + 1023) / 1024;
    int start = tid * CHK;
    int end   = min(start + CHK, NN);
    int sum = 0;
    for (int i = start; i < end; i++) sum += g_deg[i];
    s[tid] = sum;
    __syncthreads();
    for (int off = 1; off < 1024; off <<= 1) {
        int v = (tid >= off) ? s[tid - off] : 0;
        __syncthreads();
        s[tid] += v;
        __syncthreads();
    }
    int run = s[tid] - sum;
    for (int i = start; i < end; i++) {
        g_rowptr[i] = run;
        g_cursor[i] = run;
        run += g_deg[i];
    }
    if (tid == 1023) g_rowptr[NN] = s[1023];
}

__global__ void k_scatter(const int* __restrict__ ei) {
    int t = blockIdx.x * blockDim.x + threadIdx.x;
    if (t >= TT) return;
    int sv, dv;
    if (t < EE) { sv = ei[t]; dv = ei[EE + t]; }
    else        { sv = dv = t - EE; }
    int pos = atomicAdd(&g_cursor[dv], 1);
    g_srcs[pos] = sv;
}

// ---------------- fp16 tensor-core GEMM + fused alpha/fp16 epilogue ---------
#define BM 128
#define BN 64
#define BK 32
#define LDAH (BK + 8)   // 40 halfs
#define LDBH (BN + 8)   // 72 halfs
#define ASZH (BM * LDAH)
#define BSZH (BK * LDBH)
#define LDC (BN + 4)
#define SMEM_BYTES 34816

template <int LAYER>
__global__ void __launch_bounds__(256) k_gemm(const float* __restrict__ Aext,
                                              const float* __restrict__ B,
                                              const float* __restrict__ att_s,
                                              const float* __restrict__ att_d,
                                              int M, int K) {
    __shared__ __align__(16) char smbuf[SMEM_BYTES];
    __half* Ash = (__half*)smbuf;                     // [2][BM][LDAH]
    __half* Bsh = (__half*)(smbuf + 2 * ASZH * 2);    // [2][BK][LDBH]

    const int tid = threadIdx.x;
    const int wid = tid >> 5;
    const int wm = wid >> 1;
    const int wn = wid & 1;
    const int m0 = blockIdx.y * BM;
    const int n0 = blockIdx.x * BN;

    const int brow[2] = { (tid + 0) >> 4, (tid + 256) >> 4 };
    const int bcol = (tid & 15) * 4;
    float4 rbf[2];

    const int arow_f[4] = { (tid + 0) >> 3, (tid + 256) >> 3, (tid + 512) >> 3, (tid + 768) >> 3 };
    const int acol_f = (tid & 7) * 4;
    float4 raf[4];
    const int arow_h[2] = { (tid + 0) >> 2, (tid + 256) >> 2 };
    const int acol_h = (tid & 3) * 8;
    uint4 rah[2];

    auto loadG = [&](int k0) {
        if (LAYER == 1) {
#pragma unroll
            for (int i = 0; i < 4; i++) {
                float4 v = make_float4(0.f, 0.f, 0.f, 0.f);
                if (m0 + arow_f[i] < M)
                    v = *(const float4*)&Aext[(size_t)(m0 + arow_f[i]) * K + k0 + acol_f];
                raf[i] = v;
            }
        } else {
#pragma unroll
            for (int i = 0; i < 2; i++)
                rah[i] = *(const uint4*)&g_x1h[(size_t)(m0 + arow_h[i]) * K + k0 + acol_h];
        }
#pragma unroll
        for (int i = 0; i < 2; i++)
            rbf[i] = *(const float4*)&B[(size_t)(k0 + brow[i]) * CHN + n0 + bcol];
    };
    auto storeS = [&](int buf) {
        if (LAYER == 1) {
#pragma unroll
            for (int i = 0; i < 4; i++) {
                __half2* p = (__half2*)&Ash[buf * ASZH + arow_f[i] * LDAH + acol_f];
                p[0] = __floats2half2_rn(raf[i].x, raf[i].y);
                p[1] = __floats2half2_rn(raf[i].z, raf[i].w);
            }
        } else {
#pragma unroll
            for (int i = 0; i < 2; i++)
                *(uint4*)&Ash[buf * ASZH + arow_h[i] * LDAH + acol_h] = rah[i];
        }
#pragma unroll
        for (int i = 0; i < 2; i++) {
            __half2* p = (__half2*)&Bsh[buf * BSZH + brow[i] * LDBH + bcol];
            p[0] = __floats2half2_rn(rbf[i].x, rbf[i].y);
            p[1] = __floats2half2_rn(rbf[i].z, rbf[i].w);
        }
    };

    wmma::fragment<wmma::accumulator, 16, 16, 16, float> c[2][2];
#pragma unroll
    for (int i = 0; i < 2; i++)
#pragma unroll
        for (int j = 0; j < 2; j++) wmma::fill_fragment(c[i][j], 0.f);

    loadG(0);
    storeS(0);
    __syncthreads();

    int buf = 0;
    for (int k0 = 0; k0 < K; k0 += BK) {
        const bool has_next = (k0 + BK) < K;
        if (has_next) loadG(k0 + BK);

#pragma unroll
        for (int kk = 0; kk < BK; kk += 16) {
            wmma::fragment<wmma::matrix_a, 16, 16, 16, __half, wmma::row_major> a[2];
            wmma::fragment<wmma::matrix_b, 16, 16, 16, __half, wmma::row_major> b[2];
#pragma unroll
            for (int i = 0; i < 2; i++)
                wmma::load_matrix_sync(a[i], &Ash[buf * ASZH + (wm * 32 + i * 16) * LDAH + kk], LDAH);
#pragma unroll
            for (int j = 0; j < 2; j++)
                wmma::load_matrix_sync(b[j], &Bsh[buf * BSZH + kk * LDBH + wn * 32 + j * 16], LDBH);
#pragma unroll
            for (int i = 0; i < 2; i++)
#pragma unroll
                for (int j = 0; j < 2; j++)
                    wmma::mma_sync(c[i][j], a[i], b[j], c[i][j]);
        }

        if (has_next) {
            storeS(buf ^ 1);
            __syncthreads();
            buf ^= 1;
        }
    }

    // ---- epilogue ----
    __syncthreads();
    float* Cs = (float*)smbuf;   // [BM][LDC]
#pragma unroll
    for (int i = 0; i < 2; i++)
#pragma unroll
        for (int j = 0; j < 2; j++)
            wmma::store_matrix_sync(
                &Cs[(wm * 32 + i * 16) * LDC + wn * 32 + j * 16],
                c[i][j], LDC, wmma::mem_row_major);
    __syncthreads();

    {
        const int r = tid >> 1;
        const int half = tid & 1;
        const float* crow = &Cs[r * LDC + half * 32];

        uint4 w[4];
        __half2* wh = (__half2*)w;
#pragma unroll
        for (int i = 0; i < 16; i++)
            wh[i] = __floats2half2_rn(crow[2 * i], crow[2 * i + 1]);
        uint4* dst = (uint4*)&g_h16[(size_t)(m0 + r) * CHN + n0 + half * 32];
#pragma unroll
        for (int i = 0; i < 4; i++) dst[i] = w[i];

        const int hh = n0 >> 6;
        const float* asp = att_s + n0 + half * 32;
        const float* adp = att_d + n0 + half * 32;
        float s = 0.f, d = 0.f;
#pragma unroll
        for (int cc = 0; cc < 32; cc++) {
            float v = crow[cc];
            s += v * asp[cc];
            d += v * adp[cc];
        }
        s += __shfl_xor_sync(0xffffffffu, s, 1);
        d += __shfl_xor_sync(0xffffffffu, d, 1);
        if (half == 0 && m0 + r < NN) {
            g_as[(m0 + r) * 4 + hh] = s;
            g_ad[(m0 + r) * 4 + hh] = d;
        }
    }
}

// ---------------- fused edge + online-softmax + aggregation (warp/node) -----
__device__ __forceinline__ float lrelu(float v) { return v > 0.f ? v : 0.2f * v; }

__device__ __forceinline__ void online_upd(float& m, float& s, float e) {
    float mn = fmaxf(m, e);
    s = s * __expf(m - mn) + __expf(e - mn);
    m = mn;
}
__device__ __forceinline__ void online_red(float& m, float& s, int o) {
    float mo = __shfl_xor_sync(0xffffffffu, m, o);
    float so = __shfl_xor_sync(0xffffffffu, s, o);
    float mn = fmaxf(m, mo);
    s = s * __expf(m - mn) + so * __expf(mo - mn);
    m = mn;
}

template <int LAYER>
__global__ void __launch_bounds__(256) k_agg(const float* __restrict__ bias,
                                             float* __restrict__ outext) {
    const int gw = (blockIdx.x * blockDim.x + threadIdx.x) >> 5;
    const int lane = threadIdx.x & 31;
    if (gw >= NN) return;
    const int row = g_rowptr[gw];
    const int deg = g_rowptr[gw + 1] - row;

    // dst-side alpha is a warp constant
    const float4 ad4 = *(const float4*)&g_ad[gw * 4];

    // pass 1: compute logits inline (gather g_as[src]), store g_e, online (m,s)
    float4 m4 = make_float4(-1e30f, -1e30f, -1e30f, -1e30f);
    float4 s4 = make_float4(0.f, 0.f, 0.f, 0.f);
    for (int j = lane; j < deg; j += 32) {
        const int sv = g_srcs[row + j];
        const float4 as = *(const float4*)&g_as[sv * 4];
        float4 e;
        e.x = lrelu(as.x + ad4.x);
        e.y = lrelu(as.y + ad4.y);
        e.z = lrelu(as.z + ad4.z);
        e.w = lrelu(as.w + ad4.w);
        *(float4*)&g_e[(size_t)(row + j) * 4] = e;
        online_upd(m4.x, s4.x, e.x);
        online_upd(m4.y, s4.y, e.y);
        online_upd(m4.z, s4.z, e.z);
        online_upd(m4.w, s4.w, e.w);
    }
#pragma unroll
    for (int o = 16; o; o >>= 1) {
        online_red(m4.x, s4.x, o);
        online_red(m4.y, s4.y, o);
        online_red(m4.z, s4.z, o);
        online_red(m4.w, s4.w, o);
    }
    __syncwarp();   // order pass-1 g_e stores before pass-2 cross-lane reads

    const bool hi = lane >= 16;
    const float mA = hi ? m4.y : m4.x;
    const float mB = hi ? m4.w : m4.z;
    const float iA = 1.f / ((hi ? s4.y : s4.x) + 1e-16f);
    const float iB = 1.f / ((hi ? s4.w : s4.z) + 1e-16f);

    const int cA = lane * 4;
    float4 accA = make_float4(0.f, 0.f, 0.f, 0.f);
    float4 accB = make_float4(0.f, 0.f, 0.f, 0.f);

#pragma unroll 2
    for (int j = 0; j < deg; j++) {
        const float4 e = *(const float4*)&g_e[(size_t)(row + j) * 4];   // broadcast
        const int src = g_srcs[row + j];                                // broadcast
        const float aA = __expf((hi ? e.y : e.x) - mA) * iA;
        const float aB = __expf((hi ? e.w : e.z) - mB) * iB;
        const uint2 u0 = *(const uint2*)(g_h16 + (size_t)src * CHN + cA);
        const uint2 u1 = *(const uint2*)(g_h16 + (size_t)src * CHN + 128 + cA);
        const float2 f00 = __half22float2(*(const __half2*)&u0.x);
        const float2 f01 = __half22float2(*(const __half2*)&u0.y);
        const float2 f10 = __half22float2(*(const __half2*)&u1.x);
        const float2 f11 = __half22float2(*(const __half2*)&u1.y);
        accA.x += aA * f00.x; accA.y += aA * f00.y;
        accA.z += aA * f01.x; accA.w += aA * f01.y;
        accB.x += aB * f10.x; accB.y += aB * f10.y;
        accB.z += aB * f11.x; accB.w += aB * f11.y;
    }

    if (LAYER == 1) {
        const float4 bA = *(const float4*)&bias[cA];
        const float4 bB = *(const float4*)&bias[128 + cA];
        uint2 oA, oB;
        ((__half2*)&oA)[0] = __floats2half2_rn(fmaxf(accA.x + bA.x, 0.f), fmaxf(accA.y + bA.y, 0.f));
        ((__half2*)&oA)[1] = __floats2half2_rn(fmaxf(accA.z + bA.z, 0.f), fmaxf(accA.w + bA.w, 0.f));
        ((__half2*)&oB)[0] = __floats2half2_rn(fmaxf(accB.x + bB.x, 0.f), fmaxf(accB.y + bB.y, 0.f));
        ((__half2*)&oB)[1] = __floats2half2_rn(fmaxf(accB.z + bB.z, 0.f), fmaxf(accB.w + bB.w, 0.f));
        *(uint2*)&g_x1h[(size_t)gw * CHN + cA] = oA;
        *(uint2*)&g_x1h[(size_t)gw * CHN + 128 + cA] = oB;
    } else {
        float4 r;
        r.x = accA.x + accB.x;
        r.y = accA.y + accB.y;
        r.z = accA.z + accB.z;
        r.w = accA.w + accB.w;
        r.x += __shfl_xor_sync(0xffffffffu, r.x, 16);
        r.y += __shfl_xor_sync(0xffffffffu, r.y, 16);
        r.z += __shfl_xor_sync(0xffffffffu, r.z, 16);
        r.w += __shfl_xor_sync(0xffffffffu, r.w, 16);
        if (!hi) {
            const float4 b = *(const float4*)&bias[lane * 4];
            float4 o;
            o.x = 0.25f * r.x + b.x;
            o.y = 0.25f * r.y + b.y;
            o.z = 0.25f * r.z + b.z;
            o.w = 0.25f * r.w + b.w;
            *(float4*)&outext[(size_t)gw * C2 + lane * 4] = o;
        }
    }
}

// ---------------- launch -----------------------------------------------------
extern "C" void kernel_launch(void* const* d_in, const int* in_sizes, int n_in,
                              void* d_out, int out_size) {
    const float* x   = (const float*)d_in[0];
    const int*   ei  = (const int*)d_in[1];
    const float* W1  = (const float*)d_in[2];
    const float* as1 = (const float*)d_in[3];
    const float* ad1 = (const float*)d_in[4];
    const float* b1  = (const float*)d_in[5];
    const float* W2  = (const float*)d_in[6];
    const float* as2 = (const float*)d_in[7];
    const float* ad2 = (const float*)d_in[8];
    const float* b2  = (const float*)d_in[9];
    float* out = (float*)d_out;

    // CSR build (shared by both layers)
    k_zero_deg<<<(NN + 255) / 256, 256>>>();
    k_hist<<<(TT + 255) / 256, 256>>>(ei);
    k_scan<<<1, 1024>>>();
    k_scatter<<<(TT + 255) / 256, 256>>>(ei);

    dim3 gemm_grid(CHN / BN, NPAD / BM);
    const int agg_blocks = (NN * 32 + 255) / 256;

    // ----- layer 1 -----
    k_gemm<1><<<gemm_grid, 256>>>(x, W1, as1, ad1, NN, 128);
    k_agg<1><<<agg_blocks, 256>>>(b1, nullptr);

    // ----- layer 2 -----
    k_gemm<2><<<gemm_grid, 256>>>(nullptr, W2, as2, ad2, NN, 256);
    k_agg<2><<<agg_blocks, 256>>>(b2, out);
}

// round 12
// speedup vs baseline: 1.2829x; 1.2829x over previous
#include <cuda_runtime.h>
#include <cuda_fp16.h>
#include <mma.h>
using namespace nvcuda;

#define NN 50000
#define NPAD 50048     // NN rounded up to 128 (GEMM tile)
#define EE 800000
#define TT (EE + NN)
#define HH 4
#define CHN 256        // H * C (both layers)
#define C2  64
#define SCAN_BLKS 196  // 196*256 = 50176 >= NN

// ---------------- scratch (device globals; no allocation allowed) ----------
__device__ __align__(16) __half g_h16[(size_t)NPAD * CHN];  // GEMM out (fp16)
__device__ __align__(16) __half g_x1h[(size_t)NPAD * CHN];  // relu(layer1 out), fp16
__device__ __align__(16) float g_as[NN * HH];
__device__ __align__(16) float g_ad[NN * HH];
__device__ __align__(16) float g_e[(size_t)TT * HH];        // CSR-ordered logits
__device__ int   g_deg[NN];
__device__ int   g_pref[NN];        // within-block exclusive prefix
__device__ int   g_bsum[SCAN_BLKS];
__device__ int   g_boff[SCAN_BLKS];
__device__ int   g_rowptr[NN + 1];
__device__ int   g_cursor[NN];
__device__ int   g_srcs[TT];

// ---------------- streams for fork/join overlap (static init, never freed) --
struct StreamsInit {
    cudaStream_t s2;
    cudaEvent_t fork, join;
    StreamsInit() {
        cudaStreamCreateWithFlags(&s2, cudaStreamNonBlocking);
        cudaEventCreateWithFlags(&fork, cudaEventDisableTiming);
        cudaEventCreateWithFlags(&join, cudaEventDisableTiming);
    }
};
static StreamsInit g_str;

// ---------------- CSR build -------------------------------------------------
__global__ void k_zero_deg() {
    int i = blockIdx.x * blockDim.x + threadIdx.x;
    if (i < NN) g_deg[i] = 0;
}

__global__ void k_hist(const int* __restrict__ ei) {
    int t = blockIdx.x * blockDim.x + threadIdx.x;
    if (t >= TT) return;
    int d = (t < EE) ? ei[EE + t] : (t - EE);
    atomicAdd(&g_deg[d], 1);
}

// two-level exclusive scan of g_deg -> g_rowptr/g_cursor
__global__ void k_scan1() {
    __shared__ int s[256];
    const int tid = threadIdx.x;
    const int i = blockIdx.x * 256 + tid;
    int v = (i < NN) ? g_deg[i] : 0;
    s[tid] = v;
    __syncthreads();
#pragma unroll
    for (int off = 1; off < 256; off <<= 1) {
        int t = (tid >= off) ? s[tid - off] : 0;
        __syncthreads();
        s[tid] += t;
        __syncthreads();
    }
    if (i < NN) g_pref[i] = s[tid] - v;          // exclusive within block
    if (tid == 255) g_bsum[blockIdx.x] = s[255]; // block total
}

__global__ void k_scan2() {
    __shared__ int s[SCAN_BLKS];
    const int tid = threadIdx.x;                 // 256 threads
    int v = (tid < SCAN_BLKS) ? g_bsum[tid] : 0;
    if (tid < SCAN_BLKS) s[tid] = v;
    __syncthreads();
    for (int off = 1; off < SCAN_BLKS; off <<= 1) {
        int t = (tid >= off && tid < SCAN_BLKS) ? s[tid - off] : 0;
        __syncthreads();
        if (tid < SCAN_BLKS) s[tid] += t;
        __syncthreads();
    }
    if (tid < SCAN_BLKS) g_boff[tid] = s[tid] - v;   // exclusive block offset
    if (tid == SCAN_BLKS - 1) g_rowptr[NN] = s[SCAN_BLKS - 1];
}

__global__ void k_scan3() {
    const int i = blockIdx.x * 256 + threadIdx.x;
    if (i < NN) {
        int r = g_pref[i] + g_boff[blockIdx.x];
        g_rowptr[i] = r;
        g_cursor[i] = r;
    }
}

__global__ void k_scatter(const int* __restrict__ ei) {
    int t = blockIdx.x * blockDim.x + threadIdx.x;
    if (t >= TT) return;
    int sv, dv;
    if (t < EE) { sv = ei[t]; dv = ei[EE + t]; }
    else        { sv = dv = t - EE; }
    int pos = atomicAdd(&g_cursor[dv], 1);
    g_srcs[pos] = sv;
}

// ---------------- fp16 tensor-core GEMM + fused alpha/fp16 epilogue ---------
#define BM 128
#define BN 64
#define BK 32
#define LDAH (BK + 8)   // 40 halfs
#define LDBH (BN + 8)   // 72 halfs
#define ASZH (BM * LDAH)
#define BSZH (BK * LDBH)
#define LDC (BN + 4)
#define SMEM_BYTES 34816

template <int LAYER>
__global__ void __launch_bounds__(256) k_gemm(const float* __restrict__ Aext,
                                              const float* __restrict__ B,
                                              const float* __restrict__ att_s,
                                              const float* __restrict__ att_d,
                                              int M, int K) {
    __shared__ __align__(16) char smbuf[SMEM_BYTES];
    __half* Ash = (__half*)smbuf;                     // [2][BM][LDAH]
    __half* Bsh = (__half*)(smbuf + 2 * ASZH * 2);    // [2][BK][LDBH]

    const int tid = threadIdx.x;
    const int wid = tid >> 5;
    const int wm = wid >> 1;
    const int wn = wid & 1;
    const int m0 = blockIdx.y * BM;
    const int n0 = blockIdx.x * BN;

    const int brow[2] = { (tid + 0) >> 4, (tid + 256) >> 4 };
    const int bcol = (tid & 15) * 4;
    float4 rbf[2];

    const int arow_f[4] = { (tid + 0) >> 3, (tid + 256) >> 3, (tid + 512) >> 3, (tid + 768) >> 3 };
    const int acol_f = (tid & 7) * 4;
    float4 raf[4];
    const int arow_h[2] = { (tid + 0) >> 2, (tid + 256) >> 2 };
    const int acol_h = (tid & 3) * 8;
    uint4 rah[2];

    auto loadG = [&](int k0) {
        if (LAYER == 1) {
#pragma unroll
            for (int i = 0; i < 4; i++) {
                float4 v = make_float4(0.f, 0.f, 0.f, 0.f);
                if (m0 + arow_f[i] < M)
                    v = *(const float4*)&Aext[(size_t)(m0 + arow_f[i]) * K + k0 + acol_f];
                raf[i] = v;
            }
        } else {
#pragma unroll
            for (int i = 0; i < 2; i++)
                rah[i] = *(const uint4*)&g_x1h[(size_t)(m0 + arow_h[i]) * K + k0 + acol_h];
        }
#pragma unroll
        for (int i = 0; i < 2; i++)
            rbf[i] = *(const float4*)&B[(size_t)(k0 + brow[i]) * CHN + n0 + bcol];
    };
    auto storeS = [&](int buf) {
        if (LAYER == 1) {
#pragma unroll
            for (int i = 0; i < 4; i++) {
                __half2* p = (__half2*)&Ash[buf * ASZH + arow_f[i] * LDAH + acol_f];
                p[0] = __floats2half2_rn(raf[i].x, raf[i].y);
                p[1] = __floats2half2_rn(raf[i].z, raf[i].w);
            }
        } else {
#pragma unroll
            for (int i = 0; i < 2; i++)
                *(uint4*)&Ash[buf * ASZH + arow_h[i] * LDAH + acol_h] = rah[i];
        }
#pragma unroll
        for (int i = 0; i < 2; i++) {
            __half2* p = (__half2*)&Bsh[buf * BSZH + brow[i] * LDBH + bcol];
            p[0] = __floats2half2_rn(rbf[i].x, rbf[i].y);
            p[1] = __floats2half2_rn(rbf[i].z, rbf[i].w);
        }
    };

    wmma::fragment<wmma::accumulator, 16, 16, 16, float> c[2][2];
#pragma unroll
    for (int i = 0; i < 2; i++)
#pragma unroll
        for (int j = 0; j < 2; j++) wmma::fill_fragment(c[i][j], 0.f);

    loadG(0);
    storeS(0);
    __syncthreads();

    int buf = 0;
    for (int k0 = 0; k0 < K; k0 += BK) {
        const bool has_next = (k0 + BK) < K;
        if (has_next) loadG(k0 + BK);

#pragma unroll
        for (int kk = 0; kk < BK; kk += 16) {
            wmma::fragment<wmma::matrix_a, 16, 16, 16, __half, wmma::row_major> a[2];
            wmma::fragment<wmma::matrix_b, 16, 16, 16, __half, wmma::row_major> b[2];
#pragma unroll
            for (int i = 0; i < 2; i++)
                wmma::load_matrix_sync(a[i], &Ash[buf * ASZH + (wm * 32 + i * 16) * LDAH + kk], LDAH);
#pragma unroll
            for (int j = 0; j < 2; j++)
                wmma::load_matrix_sync(b[j], &Bsh[buf * BSZH + kk * LDBH + wn * 32 + j * 16], LDBH);
#pragma unroll
            for (int i = 0; i < 2; i++)
#pragma unroll
                for (int j = 0; j < 2; j++)
                    wmma::mma_sync(c[i][j], a[i], b[j], c[i][j]);
        }

        if (has_next) {
            storeS(buf ^ 1);
            __syncthreads();
            buf ^= 1;
        }
    }

    // ---- epilogue ----
    __syncthreads();
    float* Cs = (float*)smbuf;   // [BM][LDC]
#pragma unroll
    for (int i = 0; i < 2; i++)
#pragma unroll
        for (int j = 0; j < 2; j++)
            wmma::store_matrix_sync(
                &Cs[(wm * 32 + i * 16) * LDC + wn * 32 + j * 16],
                c[i][j], LDC, wmma::mem_row_major);
    __syncthreads();

    {
        const int r = tid >> 1;
        const int half = tid & 1;
        const float* crow = &Cs[r * LDC + half * 32];

        uint4 w[4];
        __half2* wh = (__half2*)w;
#pragma unroll
        for (int i = 0; i < 16; i++)
            wh[i] = __floats2half2_rn(crow[2 * i], crow[2 * i + 1]);
        uint4* dst = (uint4*)&g_h16[(size_t)(m0 + r) * CHN + n0 + half * 32];
#pragma unroll
        for (int i = 0; i < 4; i++) dst[i] = w[i];

        const int hh = n0 >> 6;
        const float* asp = att_s + n0 + half * 32;
        const float* adp = att_d + n0 + half * 32;
        float s = 0.f, d = 0.f;
#pragma unroll
        for (int cc = 0; cc < 32; cc++) {
            float v = crow[cc];
            s += v * asp[cc];
            d += v * adp[cc];
        }
        s += __shfl_xor_sync(0xffffffffu, s, 1);
        d += __shfl_xor_sync(0xffffffffu, d, 1);
        if (half == 0 && m0 + r < NN) {
            g_as[(m0 + r) * 4 + hh] = s;
            g_ad[(m0 + r) * 4 + hh] = d;
        }
    }
}

// ---------------- fused edge + online-softmax + aggregation (warp/node) -----
__device__ __forceinline__ float lrelu(float v) { return v > 0.f ? v : 0.2f * v; }

__device__ __forceinline__ void online_upd(float& m, float& s, float e) {
    float mn = fmaxf(m, e);
    s = s * __expf(m - mn) + __expf(e - mn);
    m = mn;
}
__device__ __forceinline__ void online_red(float& m, float& s, int o) {
    float mo = __shfl_xor_sync(0xffffffffu, m, o);
    float so = __shfl_xor_sync(0xffffffffu, s, o);
    float mn = fmaxf(m, mo);
    s = s * __expf(m - mn) + so * __expf(mo - mn);
    m = mn;
}

template <int LAYER>
__global__ void __launch_bounds__(256) k_agg(const float* __restrict__ bias,
                                             float* __restrict__ outext) {
    const int gw = (blockIdx.x * blockDim.x + threadIdx.x) >> 5;
    const int lane = threadIdx.x & 31;
    if (gw >= NN) return;
    const int row = g_rowptr[gw];
    const int deg = g_rowptr[gw + 1] - row;

    const float4 ad4 = *(const float4*)&g_ad[gw * 4];

    float4 m4 = make_float4(-1e30f, -1e30f, -1e30f, -1e30f);
    float4 s4 = make_float4(0.f, 0.f, 0.f, 0.f);
    for (int j = lane; j < deg; j += 32) {
        const int sv = g_srcs[row + j];
        const float4 as = *(const float4*)&g_as[sv * 4];
        float4 e;
        e.x = lrelu(as.x + ad4.x);
        e.y = lrelu(as.y + ad4.y);
        e.z = lrelu(as.z + ad4.z);
        e.w = lrelu(as.w + ad4.w);
        *(float4*)&g_e[(size_t)(row + j) * 4] = e;
        online_upd(m4.x, s4.x, e.x);
        online_upd(m4.y, s4.y, e.y);
        online_upd(m4.z, s4.z, e.z);
        online_upd(m4.w, s4.w, e.w);
    }
#pragma unroll
    for (int o = 16; o; o >>= 1) {
        online_red(m4.x, s4.x, o);
        online_red(m4.y, s4.y, o);
        online_red(m4.z, s4.z, o);
        online_red(m4.w, s4.w, o);
    }
    __syncwarp();

    const bool hi = lane >= 16;
    const float mA = hi ? m4.y : m4.x;
    const float mB = hi ? m4.w : m4.z;
    const float iA = 1.f / ((hi ? s4.y : s4.x) + 1e-16f);
    const float iB = 1.f / ((hi ? s4.w : s4.z) + 1e-16f);

    const int cA = lane * 4;
    float4 accA = make_float4(0.f, 0.f, 0.f, 0.f);
    float4 accB = make_float4(0.f, 0.f, 0.f, 0.f);

#pragma unroll 2
    for (int j = 0; j < deg; j++) {
        const float4 e = *(const float4*)&g_e[(size_t)(row + j) * 4];
        const int src = g_srcs[row + j];
        const float aA = __expf((hi ? e.y : e.x) - mA) * iA;
        const float aB = __expf((hi ? e.w : e.z) - mB) * iB;
        const uint2 u0 = *(const uint2*)(g_h16 + (size_t)src * CHN + cA);
        const uint2 u1 = *(const uint2*)(g_h16 + (size_t)src * CHN + 128 + cA);
        const float2 f00 = __half22float2(*(const __half2*)&u0.x);
        const float2 f01 = __half22float2(*(const __half2*)&u0.y);
        const float2 f10 = __half22float2(*(const __half2*)&u1.x);
        const float2 f11 = __half22float2(*(const __half2*)&u1.y);
        accA.x += aA * f00.x; accA.y += aA * f00.y;
        accA.z += aA * f01.x; accA.w += aA * f01.y;
        accB.x += aB * f10.x; accB.y += aB * f10.y;
        accB.z += aB * f11.x; accB.w += aB * f11.y;
    }

    if (LAYER == 1) {
        const float4 bA = *(const float4*)&bias[cA];
        const float4 bB = *(const float4*)&bias[128 + cA];
        uint2 oA, oB;
        ((__half2*)&oA)[0] = __floats2half2_rn(fmaxf(accA.x + bA.x, 0.f), fmaxf(accA.y + bA.y, 0.f));
        ((__half2*)&oA)[1] = __floats2half2_rn(fmaxf(accA.z + bA.z, 0.f), fmaxf(accA.w + bA.w, 0.f));
        ((__half2*)&oB)[0] = __floats2half2_rn(fmaxf(accB.x + bB.x, 0.f), fmaxf(accB.y + bB.y, 0.f));
        ((__half2*)&oB)[1] = __floats2half2_rn(fmaxf(accB.z + bB.z, 0.f), fmaxf(accB.w + bB.w, 0.f));
        *(uint2*)&g_x1h[(size_t)gw * CHN + cA] = oA;
        *(uint2*)&g_x1h[(size_t)gw * CHN + 128 + cA] = oB;
    } else {
        float4 r;
        r.x = accA.x + accB.x;
        r.y = accA.y + accB.y;
        r.z = accA.z + accB.z;
        r.w = accA.w + accB.w;
        r.x += __shfl_xor_sync(0xffffffffu, r.x, 16);
        r.y += __shfl_xor_sync(0xffffffffu, r.y, 16);
        r.z += __shfl_xor_sync(0xffffffffu, r.z, 16);
        r.w += __shfl_xor_sync(0xffffffffu, r.w, 16);
        if (!hi) {
            const float4 b = *(const float4*)&bias[lane * 4];
            float4 o;
            o.x = 0.25f * r.x + b.x;
            o.y = 0.25f * r.y + b.y;
            o.z = 0.25f * r.z + b.z;
            o.w = 0.25f * r.w + b.w;
            *(float4*)&outext[(size_t)gw * C2 + lane * 4] = o;
        }
    }
}

// ---------------- launch -----------------------------------------------------
extern "C" void kernel_launch(void* const* d_in, const int* in_sizes, int n_in,
                              void* d_out, int out_size) {
    const float* x   = (const float*)d_in[0];
    const int*   ei  = (const int*)d_in[1];
    const float* W1  = (const float*)d_in[2];
    const float* as1 = (const float*)d_in[3];
    const float* ad1 = (const float*)d_in[4];
    const float* b1  = (const float*)d_in[5];
    const float* W2  = (const float*)d_in[6];
    const float* as2 = (const float*)d_in[7];
    const float* ad2 = (const float*)d_in[8];
    const float* b2  = (const float*)d_in[9];
    float* out = (float*)d_out;

    dim3 gemm_grid(CHN / BN, NPAD / BM);
    const int agg_blocks = (NN * 32 + 255) / 256;

    // fork: GEMM-1 on side stream, CSR build on main stream (independent)
    cudaEventRecord(g_str.fork, 0);
    cudaStreamWaitEvent(g_str.s2, g_str.fork, 0);
    k_gemm<1><<<gemm_grid, 256, 0, g_str.s2>>>(x, W1, as1, ad1, NN, 128);
    cudaEventRecord(g_str.join, g_str.s2);

    k_zero_deg<<<(NN + 255) / 256, 256>>>();
    k_hist<<<(TT + 255) / 256, 256>>>(ei);
    k_scan1<<<SCAN_BLKS, 256>>>();
    k_scan2<<<1, 256>>>();
    k_scan3<<<SCAN_BLKS, 256>>>();
    k_scatter<<<(TT + 255) / 256, 256>>>(ei);

    // join: agg<1> needs CSR (main) + GEMM-1 (s2)
    cudaStreamWaitEvent(0, g_str.join, 0);
    k_agg<1><<<agg_blocks, 256>>>(b1, nullptr);

    // ----- layer 2 (serial chain) -----
    k_gemm<2><<<gemm_grid, 256>>>(nullptr, W2, as2, ad2, NN, 256);
    k_agg<2><<<agg_blocks, 256>>>(b2, out);
}

// round 13
// speedup vs baseline: 1.4194x; 1.1064x over previous
#include <cuda_runtime.h>
#include <cuda_fp16.h>
#include <mma.h>
using namespace nvcuda;

#define NN 50000
#define NPAD 50048     // NN rounded up to 128 (GEMM tile)
#define EE 800000
#define TT (EE + NN)
#define HH 4
#define CHN 256        // H * C (both layers)
#define C2  64
#define SCAN_BLKS 196  // 196*256 = 50176 >= NN

// ---------------- scratch (device globals; no allocation allowed) ----------
__device__ __align__(16) __half g_h16[(size_t)NPAD * CHN];  // GEMM out (fp16)
__device__ __align__(16) __half g_x1h[(size_t)NPAD * CHN];  // relu(layer1 out), fp16
__device__ __align__(16) float g_as[NN * HH];
__device__ __align__(16) float g_ad[NN * HH];
__device__ __align__(16) float g_e[(size_t)TT * HH];        // CSR-ordered logits
__device__ int   g_deg[NN];
__device__ int   g_pref[NN];
__device__ int   g_bsum[SCAN_BLKS];
__device__ int   g_boff[SCAN_BLKS];
__device__ int   g_rowptr[NN + 1];
__device__ int   g_cursor[NN];
__device__ int   g_srcs[TT];

// ---------------- streams for fork/join overlap (static init, never freed) --
struct StreamsInit {
    cudaStream_t s2;
    cudaEvent_t fork, join;
    StreamsInit() {
        cudaStreamCreateWithFlags(&s2, cudaStreamNonBlocking);
        cudaEventCreateWithFlags(&fork, cudaEventDisableTiming);
        cudaEventCreateWithFlags(&join, cudaEventDisableTiming);
    }
};
static StreamsInit g_str;

// ---------------- CSR build -------------------------------------------------
__global__ void k_zero_deg() {
    int i = blockIdx.x * blockDim.x + threadIdx.x;
    if (i < NN) g_deg[i] = 0;
}

__global__ void k_hist(const int* __restrict__ ei) {
    int t = blockIdx.x * blockDim.x + threadIdx.x;
    if (t >= TT) return;
    int d = (t < EE) ? ei[EE + t] : (t - EE);
    atomicAdd(&g_deg[d], 1);
}

__global__ void k_scan1() {
    __shared__ int s[256];
    const int tid = threadIdx.x;
    const int i = blockIdx.x * 256 + tid;
    int v = (i < NN) ? g_deg[i] : 0;
    s[tid] = v;
    __syncthreads();
#pragma unroll
    for (int off = 1; off < 256; off <<= 1) {
        int t = (tid >= off) ? s[tid - off] : 0;
        __syncthreads();
        s[tid] += t;
        __syncthreads();
    }
    if (i < NN) g_pref[i] = s[tid] - v;
    if (tid == 255) g_bsum[blockIdx.x] = s[255];
}

__global__ void k_scan2() {
    __shared__ int s[SCAN_BLKS];
    const int tid = threadIdx.x;
    int v = (tid < SCAN_BLKS) ? g_bsum[tid] : 0;
    if (tid < SCAN_BLKS) s[tid] = v;
    __syncthreads();
    for (int off = 1; off < SCAN_BLKS; off <<= 1) {
        int t = (tid >= off && tid < SCAN_BLKS) ? s[tid - off] : 0;
        __syncthreads();
        if (tid < SCAN_BLKS) s[tid] += t;
        __syncthreads();
    }
    if (tid < SCAN_BLKS) g_boff[tid] = s[tid] - v;
    if (tid == SCAN_BLKS - 1) g_rowptr[NN] = s[SCAN_BLKS - 1];
}

__global__ void k_scan3() {
    const int i = blockIdx.x * 256 + threadIdx.x;
    if (i < NN) {
        int r = g_pref[i] + g_boff[blockIdx.x];
        g_rowptr[i] = r;
        g_cursor[i] = r;
    }
}

__global__ void k_scatter(const int* __restrict__ ei) {
    int t = blockIdx.x * blockDim.x + threadIdx.x;
    if (t >= TT) return;
    int sv, dv;
    if (t < EE) { sv = ei[t]; dv = ei[EE + t]; }
    else        { sv = dv = t - EE; }
    int pos = atomicAdd(&g_cursor[dv], 1);
    g_srcs[pos] = sv;
}

// ---------------- fp16 tensor-core GEMM + fused alpha/fp16 epilogue ---------
// BM=128, BN=128, BK=32; double-buffered fp16 smem; 8 warps 4x2; warp 32x64.
#define BM 128
#define BN 128
#define BK 32
#define LDAH (BK + 8)    // 40 halfs
#define LDBH (BN + 8)    // 136 halfs
#define ASZH (BM * LDAH) // 5120 halfs/buffer
#define BSZH (BK * LDBH) // 4352 halfs/buffer
#define LDC  (64 + 4)    // Cs staging: 64-col chunk
#define SMEM_BYTES (2 * (ASZH + BSZH) * 2)   // 37888; Cs chunk 128*68*4=34816 fits

template <int LAYER>
__global__ void __launch_bounds__(256) k_gemm(const float* __restrict__ Aext,
                                              const float* __restrict__ B,
                                              const float* __restrict__ att_s,
                                              const float* __restrict__ att_d,
                                              int M, int K) {
    __shared__ __align__(16) char smbuf[SMEM_BYTES];
    __half* Ash = (__half*)smbuf;                     // [2][BM][LDAH]
    __half* Bsh = (__half*)(smbuf + 2 * ASZH * 2);    // [2][BK][LDBH]

    const int tid = threadIdx.x;
    const int wid = tid >> 5;
    const int wm = wid >> 1;      // 0..3 -> rows wm*32
    const int wn = wid & 1;       // 0..1 -> cols wn*64
    const int m0 = blockIdx.y * BM;
    const int n0 = blockIdx.x * BN;

    // B tile: 32x128 floats = 1024 float4 -> 4/thread
    const int brow[4] = { (tid + 0) >> 5, (tid + 256) >> 5, (tid + 512) >> 5, (tid + 768) >> 5 };
    const int bcol = (tid & 31) * 4;
    float4 rbf[4];

    // A tile fp32 (layer1): 128x32 floats = 1024 float4 -> 4/thread
    const int arow_f[4] = { (tid + 0) >> 3, (tid + 256) >> 3, (tid + 512) >> 3, (tid + 768) >> 3 };
    const int acol_f = (tid & 7) * 4;
    float4 raf[4];
    // A tile fp16 (layer2): 128x32 halfs = 512 uint4 -> 2/thread
    const int arow_h[2] = { (tid + 0) >> 2, (tid + 256) >> 2 };
    const int acol_h = (tid & 3) * 8;
    uint4 rah[2];

    auto loadG = [&](int k0) {
        if (LAYER == 1) {
#pragma unroll
            for (int i = 0; i < 4; i++) {
                float4 v = make_float4(0.f, 0.f, 0.f, 0.f);
                if (m0 + arow_f[i] < M)
                    v = *(const float4*)&Aext[(size_t)(m0 + arow_f[i]) * K + k0 + acol_f];
                raf[i] = v;
            }
        } else {
#pragma unroll
            for (int i = 0; i < 2; i++)
                rah[i] = *(const uint4*)&g_x1h[(size_t)(m0 + arow_h[i]) * K + k0 + acol_h];
        }
#pragma unroll
        for (int i = 0; i < 4; i++)
            rbf[i] = *(const float4*)&B[(size_t)(k0 + brow[i]) * CHN + n0 + bcol];
    };
    auto storeS = [&](int buf) {
        if (LAYER == 1) {
#pragma unroll
            for (int i = 0; i < 4; i++) {
                __half2* p = (__half2*)&Ash[buf * ASZH + arow_f[i] * LDAH + acol_f];
                p[0] = __floats2half2_rn(raf[i].x, raf[i].y);
                p[1] = __floats2half2_rn(raf[i].z, raf[i].w);
            }
        } else {
#pragma unroll
            for (int i = 0; i < 2; i++)
                *(uint4*)&Ash[buf * ASZH + arow_h[i] * LDAH + acol_h] = rah[i];
        }
#pragma unroll
        for (int i = 0; i < 4; i++) {
            __half2* p = (__half2*)&Bsh[buf * BSZH + brow[i] * LDBH + bcol];
            p[0] = __floats2half2_rn(rbf[i].x, rbf[i].y);
            p[1] = __floats2half2_rn(rbf[i].z, rbf[i].w);
        }
    };

    wmma::fragment<wmma::accumulator, 16, 16, 16, float> c[2][4];
#pragma unroll
    for (int i = 0; i < 2; i++)
#pragma unroll
        for (int j = 0; j < 4; j++) wmma::fill_fragment(c[i][j], 0.f);

    loadG(0);
    storeS(0);
    __syncthreads();

    int buf = 0;
    for (int k0 = 0; k0 < K; k0 += BK) {
        const bool has_next = (k0 + BK) < K;
        if (has_next) loadG(k0 + BK);

#pragma unroll
        for (int kk = 0; kk < BK; kk += 16) {
            wmma::fragment<wmma::matrix_a, 16, 16, 16, __half, wmma::row_major> a[2];
            wmma::fragment<wmma::matrix_b, 16, 16, 16, __half, wmma::row_major> b[4];
#pragma unroll
            for (int i = 0; i < 2; i++)
                wmma::load_matrix_sync(a[i], &Ash[buf * ASZH + (wm * 32 + i * 16) * LDAH + kk], LDAH);
#pragma unroll
            for (int j = 0; j < 4; j++)
                wmma::load_matrix_sync(b[j], &Bsh[buf * BSZH + kk * LDBH + wn * 64 + j * 16], LDBH);
#pragma unroll
            for (int i = 0; i < 2; i++)
#pragma unroll
                for (int j = 0; j < 4; j++)
                    wmma::mma_sync(c[i][j], a[i], b[j], c[i][j]);
        }

        if (has_next) {
            storeS(buf ^ 1);
            __syncthreads();
            buf ^= 1;
        }
    }

    // ---- epilogue: two 64-col chunks (each = one head) through smem ----
    float* Cs = (float*)smbuf;   // [BM][LDC]
    const int r = tid >> 1;
    const int half = tid & 1;
#pragma unroll
    for (int chunk = 0; chunk < 2; chunk++) {
        __syncthreads();
        if (wn == chunk) {
#pragma unroll
            for (int i = 0; i < 2; i++)
#pragma unroll
                for (int j = 0; j < 4; j++)
                    wmma::store_matrix_sync(
                        &Cs[(wm * 32 + i * 16) * LDC + j * 16],
                        c[i][j], LDC, wmma::mem_row_major);
        }
        __syncthreads();

        const float* crow = &Cs[r * LDC + half * 32];
        const int nbase = n0 + chunk * 64;

        // fp16 store of 32 channels
        uint4 w[4];
        __half2* wh = (__half2*)w;
#pragma unroll
        for (int i = 0; i < 16; i++)
            wh[i] = __floats2half2_rn(crow[2 * i], crow[2 * i + 1]);
        uint4* dst = (uint4*)&g_h16[(size_t)(m0 + r) * CHN + nbase + half * 32];
#pragma unroll
        for (int i = 0; i < 4; i++) dst[i] = w[i];

        // fused alpha dot products
        const int hh = nbase >> 6;
        const float* asp = att_s + nbase + half * 32;
        const float* adp = att_d + nbase + half * 32;
        float s = 0.f, d = 0.f;
#pragma unroll
        for (int cc = 0; cc < 32; cc++) {
            float v = crow[cc];
            s += v * asp[cc];
            d += v * adp[cc];
        }
        s += __shfl_xor_sync(0xffffffffu, s, 1);
        d += __shfl_xor_sync(0xffffffffu, d, 1);
        if (half == 0 && m0 + r < NN) {
            g_as[(m0 + r) * 4 + hh] = s;
            g_ad[(m0 + r) * 4 + hh] = d;
        }
    }
}

// ---------------- fused edge + online-softmax + aggregation (warp/node) -----
__device__ __forceinline__ float lrelu(float v) { return v > 0.f ? v : 0.2f * v; }

__device__ __forceinline__ void online_upd(float& m, float& s, float e) {
    float mn = fmaxf(m, e);
    s = s * __expf(m - mn) + __expf(e - mn);
    m = mn;
}
__device__ __forceinline__ void online_red(float& m, float& s, int o) {
    float mo = __shfl_xor_sync(0xffffffffu, m, o);
    float so = __shfl_xor_sync(0xffffffffu, s, o);
    float mn = fmaxf(m, mo);
    s = s * __expf(m - mn) + so * __expf(mo - mn);
    m = mn;
}

template <int LAYER>
__global__ void __launch_bounds__(256) k_agg(const float* __restrict__ bias,
                                             float* __restrict__ outext) {
    const int gw = (blockIdx.x * blockDim.x + threadIdx.x) >> 5;
    const int lane = threadIdx.x & 31;
    if (gw >= NN) return;
    const int row = g_rowptr[gw];
    const int deg = g_rowptr[gw + 1] - row;

    const float4 ad4 = *(const float4*)&g_ad[gw * 4];

    // pass 1: inline logits + online softmax stats
    float4 m4 = make_float4(-1e30f, -1e30f, -1e30f, -1e30f);
    float4 s4 = make_float4(0.f, 0.f, 0.f, 0.f);
    for (int j = lane; j < deg; j += 32) {
        const int sv = g_srcs[row + j];
        const float4 as = *(const float4*)&g_as[sv * 4];
        float4 e;
        e.x = lrelu(as.x + ad4.x);
        e.y = lrelu(as.y + ad4.y);
        e.z = lrelu(as.z + ad4.z);
        e.w = lrelu(as.w + ad4.w);
        *(float4*)&g_e[(size_t)(row + j) * 4] = e;
        online_upd(m4.x, s4.x, e.x);
        online_upd(m4.y, s4.y, e.y);
        online_upd(m4.z, s4.z, e.z);
        online_upd(m4.w, s4.w, e.w);
    }
#pragma unroll
    for (int o = 16; o; o >>= 1) {
        online_red(m4.x, s4.x, o);
        online_red(m4.y, s4.y, o);
        online_red(m4.z, s4.z, o);
        online_red(m4.w, s4.w, o);
    }
    __syncwarp();

    // pass 2: lane owns 8 contiguous halfs (one head)
    const int head = lane >> 3;               // 0..3
    const float m = (head == 0) ? m4.x : (head == 1) ? m4.y : (head == 2) ? m4.z : m4.w;
    const float sd = (head == 0) ? s4.x : (head == 1) ? s4.y : (head == 2) ? s4.z : s4.w;
    const float inv = 1.f / (sd + 1e-16f);
    const int cb = lane * 8;                  // half-channel base

    float acc[8];
#pragma unroll
    for (int k = 0; k < 8; k++) acc[k] = 0.f;

#pragma unroll 2
    for (int j = 0; j < deg; j++) {
        const float e = g_e[(size_t)(row + j) * 4 + head];
        const int src = g_srcs[row + j];      // broadcast
        const float a = __expf(e - m) * inv;
        const uint4 u = *(const uint4*)&g_h16[(size_t)src * CHN + cb];
        const __half2* hp = (const __half2*)&u;
#pragma unroll
        for (int k = 0; k < 4; k++) {
            const float2 f = __half22float2(hp[k]);
            acc[2 * k]     += a * f.x;
            acc[2 * k + 1] += a * f.y;
        }
    }

    if (LAYER == 1) {
        const float4 b0 = *(const float4*)&bias[cb];
        const float4 b1 = *(const float4*)&bias[cb + 4];
        uint4 o;
        __half2* oh = (__half2*)&o;
        oh[0] = __floats2half2_rn(fmaxf(acc[0] + b0.x, 0.f), fmaxf(acc[1] + b0.y, 0.f));
        oh[1] = __floats2half2_rn(fmaxf(acc[2] + b0.z, 0.f), fmaxf(acc[3] + b0.w, 0.f));
        oh[2] = __floats2half2_rn(fmaxf(acc[4] + b1.x, 0.f), fmaxf(acc[5] + b1.y, 0.f));
        oh[3] = __floats2half2_rn(fmaxf(acc[6] + b1.z, 0.f), fmaxf(acc[7] + b1.w, 0.f));
        *(uint4*)&g_x1h[(size_t)gw * CHN + cb] = o;
    } else {
        // mean over heads: lanes L, L^8, L^16, L^24 hold same within-head chans
#pragma unroll
        for (int k = 0; k < 8; k++) {
            acc[k] += __shfl_xor_sync(0xffffffffu, acc[k], 8);
            acc[k] += __shfl_xor_sync(0xffffffffu, acc[k], 16);
        }
        if (lane < 8) {
            const int c = lane * 8;           // output channels c..c+7
            const float4 b0 = *(const float4*)&bias[c];
            const float4 b1 = *(const float4*)&bias[c + 4];
            float4 o0, o1;
            o0.x = 0.25f * acc[0] + b0.x;
            o0.y = 0.25f * acc[1] + b0.y;
            o0.z = 0.25f * acc[2] + b0.z;
            o0.w = 0.25f * acc[3] + b0.w;
            o1.x = 0.25f * acc[4] + b1.x;
            o1.y = 0.25f * acc[5] + b1.y;
            o1.z = 0.25f * acc[6] + b1.z;
            o1.w = 0.25f * acc[7] + b1.w;
            *(float4*)&outext[(size_t)gw * C2 + c] = o0;
            *(float4*)&outext[(size_t)gw * C2 + c + 4] = o1;
        }
    }
}

// ---------------- launch -----------------------------------------------------
extern "C" void kernel_launch(void* const* d_in, const int* in_sizes, int n_in,
                              void* d_out, int out_size) {
    const float* x   = (const float*)d_in[0];
    const int*   ei  = (const int*)d_in[1];
    const float* W1  = (const float*)d_in[2];
    const float* as1 = (const float*)d_in[3];
    const float* ad1 = (const float*)d_in[4];
    const float* b1  = (const float*)d_in[5];
    const float* W2  = (const float*)d_in[6];
    const float* as2 = (const float*)d_in[7];
    const float* ad2 = (const float*)d_in[8];
    const float* b2  = (const float*)d_in[9];
    float* out = (float*)d_out;

    dim3 gemm_grid(CHN / BN, NPAD / BM);
    const int agg_blocks = (NN * 32 + 255) / 256;

    // fork: GEMM-1 on side stream, CSR build on main stream (independent)
    cudaEventRecord(g_str.fork, 0);
    cudaStreamWaitEvent(g_str.s2, g_str.fork, 0);
    k_gemm<1><<<gemm_grid, 256, 0, g_str.s2>>>(x, W1, as1, ad1, NN, 128);
    cudaEventRecord(g_str.join, g_str.s2);

    k_zero_deg<<<(NN + 255) / 256, 256>>>();
    k_hist<<<(TT + 255) / 256, 256>>>(ei);
    k_scan1<<<SCAN_BLKS, 256>>>();
    k_scan2<<<1, 256>>>();
    k_scan3<<<SCAN_BLKS, 256>>>();
    k_scatter<<<(TT + 255) / 256, 256>>>(ei);

    // join: agg<1> needs CSR (main) + GEMM-1 (s2)
    cudaStreamWaitEvent(0, g_str.join, 0);
    k_agg<1><<<agg_blocks, 256>>>(b1, nullptr);

    // ----- layer 2 (serial chain) -----
    k_gemm<2><<<gemm_grid, 256>>>(nullptr, W2, as2, ad2, NN, 256);
    k_agg<2><<<agg_blocks, 256>>>(b2, out);
}